// round 4
// baseline (speedup 1.0000x reference)
#include <cuda_runtime.h>
#include <cuda_fp16.h>
#include <cstdint>
#include <math.h>

#define BATCH 8192
#define IN_F  1024
#define OUT_F 1024
#define NB    8
#define KDIM  (IN_F * 9)          // 9216
#define NKNOTS 12

// Scratch (__device__ globals — sanctioned)
__device__ __half g_Ah[(size_t)BATCH * KDIM];   // [b][c*1024+i]
__device__ __half g_Wh[(size_t)OUT_F * KDIM];   // [o][c*1024+i]  (B as [N,K])

// ---------------------------------------------------------------------------
// prep_all: blocks [0,1024) build augmented W (transposed, fp16);
//           blocks [1024, 1024+32768) build augmented activations.
// ---------------------------------------------------------------------------
#define W_BLOCKS 1024
#define ACT_BLOCKS ((BATCH * IN_F) / 256)

__global__ void prep_all(const float* __restrict__ x,
                         const float* __restrict__ grid,
                         const float* __restrict__ bw,
                         const float* __restrict__ sw,
                         const float* __restrict__ sc) {
    __shared__ float tile[9][32][33];
    __shared__ float t[NKNOTS];
    const int tid = threadIdx.x;                 // 256

    if (blockIdx.x < W_BLOCKS) {
        const int i0 = (blockIdx.x & 31) * 32;
        const int o0 = (blockIdx.x >> 5) * 32;
        { // c = 0 : base_weight[o, i] — coalesced over i
            int ti = tid & 31, to = tid >> 5;
#pragma unroll
            for (int p = 0; p < 4; ++p) {
                int ol = to + p * 8;
                tile[0][ol][ti] = bw[(size_t)(o0 + ol) * IN_F + i0 + ti];
            }
        }
        { // splines — coalesced over o
            int to = tid & 31, ti = tid >> 5;
#pragma unroll
            for (int p = 0; p < 4; ++p) {
                int il = ti + p * 8;
                int i = i0 + il;
                float scale = sc[(size_t)i * OUT_F + o0 + to];
#pragma unroll
                for (int k = 0; k < NB; ++k)
                    tile[1 + k][to][il] = sw[((size_t)i * NB + k) * OUT_F + o0 + to] * scale;
            }
        }
        __syncthreads();
        { // write g_Wh[o][c*1024+i] — coalesced over i
            int il = tid & 31, ol0 = tid >> 5;
#pragma unroll
            for (int p = 0; p < 4; ++p) {
                int ol = ol0 + p * 8;
                size_t orow = (size_t)(o0 + ol) * KDIM;
#pragma unroll
                for (int c = 0; c < 9; ++c)
                    g_Wh[orow + (size_t)c * IN_F + i0 + il] =
                        __float2half_rn(tile[c][ol][il]);
            }
        }
        return;
    }

    // ---- activation part ----
    if (tid < NKNOTS) t[tid] = grid[tid];
    __syncthreads();

    int idx = (blockIdx.x - W_BLOCKS) * 256 + tid;
    int b = idx / IN_F;
    int i = idx - b * IN_F;

    float xv = x[idx];
    float s = xv / (1.0f + __expf(-xv));

    float bas[11];
#pragma unroll
    for (int j = 0; j < 11; ++j)
        bas[j] = (xv >= t[j] && xv < t[j + 1]) ? 1.0f : 0.0f;
#pragma unroll
    for (int j = 0; j < 10; ++j) {
        float l = (xv - t[j]) / (t[j + 1] - t[j]);
        float r = (t[j + 2] - xv) / (t[j + 2] - t[j + 1]);
        bas[j] = l * bas[j] + r * bas[j + 1];
    }
#pragma unroll
    for (int j = 0; j < 9; ++j) {
        float l = (xv - t[j]) / (t[j + 2] - t[j]);
        float r = (t[j + 3] - xv) / (t[j + 3] - t[j + 1]);
        bas[j] = l * bas[j] + r * bas[j + 1];
    }
#pragma unroll
    for (int j = 0; j < 8; ++j) {
        float l = (xv - t[j]) / (t[j + 3] - t[j]);
        float r = (t[j + 4] - xv) / (t[j + 4] - t[j + 1]);
        bas[j] = l * bas[j] + r * bas[j + 1];
    }

    __half* arow = g_Ah + (size_t)b * KDIM;
    arow[i] = __float2half_rn(s);
#pragma unroll
    for (int k = 0; k < NB; ++k)
        arow[(size_t)(1 + k) * IN_F + i] = __float2half_rn(bas[k]);
}

// ---------------------------------------------------------------------------
// fp16 GEMM: C[8192,1024] = A[8192,9216] @ W^T   (W stored [N,K])
// CTA 128x256xBK64, 512 thr (16 warps, warp tile 64x32), 3-stage cp.async,
// SW128 smem, ldmatrix, mma.m16n8k16 f32 accum, A-fragment double buffering.
// ---------------------------------------------------------------------------
#define BM 128
#define BN 256
#define BK 64
#define KITERS (KDIM / BK)        // 144
#define STAGES 3
#define A_BYTES (BM * BK * 2)     // 16384
#define B_BYTES (BN * BK * 2)     // 32768
#define STG_BYTES (A_BYTES + B_BYTES)          // 49152
#define GEMM_SMEM (STAGES * STG_BYTES)         // 147456

__device__ __forceinline__ uint32_t smem_u32(const void* p) {
    uint32_t a;
    asm("{ .reg .u64 t; cvta.to.shared.u64 t, %1; cvt.u32.u64 %0, t; }" : "=r"(a) : "l"(p));
    return a;
}
__device__ __forceinline__ void cp16(uint32_t dst, const void* src) {
    asm volatile("cp.async.cg.shared.global [%0], [%1], 16;\n" :: "r"(dst), "l"(src));
}
__device__ __forceinline__ void ldsm_x4(uint32_t* r, uint32_t addr) {
    asm volatile("ldmatrix.sync.aligned.m8n8.x4.shared.b16 {%0,%1,%2,%3}, [%4];"
                 : "=r"(r[0]), "=r"(r[1]), "=r"(r[2]), "=r"(r[3]) : "r"(addr));
}
__device__ __forceinline__ void mma_f16(float* c, const uint32_t* a,
                                        uint32_t b0, uint32_t b1) {
    asm volatile(
        "mma.sync.aligned.m16n8k16.row.col.f32.f16.f16.f32 "
        "{%0,%1,%2,%3}, {%4,%5,%6,%7}, {%8,%9}, {%0,%1,%2,%3};\n"
        : "+f"(c[0]), "+f"(c[1]), "+f"(c[2]), "+f"(c[3])
        : "r"(a[0]), "r"(a[1]), "r"(a[2]), "r"(a[3]), "r"(b0), "r"(b1));
}

__device__ __forceinline__ void load_stage(uint32_t sbase, int slot,
                                           int m0, int n0, int k0, int tid) {
    uint32_t sd = sbase + slot * STG_BYTES;
#pragma unroll
    for (int t = 0; t < 2; ++t) {              // A: 1024 chunks of 16B
        int idx = tid + t * 512;
        int row = idx >> 3, c = idx & 7;
        cp16(sd + row * 128 + ((c ^ (row & 7)) << 4),
             g_Ah + (size_t)(m0 + row) * KDIM + k0 + c * 8);
    }
    uint32_t sdb = sd + A_BYTES;
#pragma unroll
    for (int t = 0; t < 4; ++t) {              // B: 2048 chunks of 16B
        int idx = tid + t * 512;
        int row = idx >> 3, c = idx & 7;
        cp16(sdb + row * 128 + ((c ^ (row & 7)) << 4),
             g_Wh + (size_t)(n0 + row) * KDIM + k0 + c * 8);
    }
}

__global__ void __launch_bounds__(512, 1)
kan_gemm(float* __restrict__ C) {
    extern __shared__ char smem[];
    const uint32_t sbase = smem_u32(smem);

    const int tid = threadIdx.x;
    const int warp = tid >> 5, lane = tid & 31;
    const int wm = warp & 1;          // 2 m-warps -> 64 rows each
    const int wn = warp >> 1;         // 8 n-warps -> 32 cols each
    const int g = lane >> 2, tg = lane & 3;
    const int m0 = blockIdx.y * BM;
    const int n0 = blockIdx.x * BN;

    // ldmatrix row/ktile components (x4 for both A and B)
    const int kt = lane >> 4;                  // upper half-warp -> k-chunk +1
    int a_row[4], b_row[2];
#pragma unroll
    for (int mt = 0; mt < 4; ++mt) a_row[mt] = wm * 64 + mt * 16 + (lane & 15);
#pragma unroll
    for (int p = 0; p < 2; ++p)   b_row[p] = wn * 32 + p * 16 + (lane & 15);

    float acc[4][4][4];
#pragma unroll
    for (int a = 0; a < 4; ++a)
#pragma unroll
        for (int b = 0; b < 4; ++b)
#pragma unroll
            for (int c = 0; c < 4; ++c) acc[a][b][c] = 0.0f;

    // Prologue
#pragma unroll
    for (int s = 0; s < STAGES - 1; ++s) {
        load_stage(sbase, s, m0, n0, s * BK, tid);
        asm volatile("cp.async.commit_group;\n" ::);
    }

    uint32_t af[2][4][4];      // double-buffered A fragments
    uint32_t bp[2][4];         // B fragments (2 n-tile pairs)

    for (int it = 0; it < KITERS; ++it) {
        asm volatile("cp.async.wait_group %0;\n" :: "n"(STAGES - 2));
        __syncthreads();

        int ls = it + STAGES - 1;
        if (ls < KITERS)
            load_stage(sbase, ls % STAGES, m0, n0, ls * BK, tid);
        asm volatile("cp.async.commit_group;\n" ::);

        const uint32_t sa = sbase + (it % STAGES) * STG_BYTES;
        const uint32_t sb = sa + A_BYTES;

        // preload A fragments for kk = 0
#pragma unroll
        for (int mt = 0; mt < 4; ++mt) {
            int r = a_row[mt];
            ldsm_x4(af[0][mt], sa + r * 128 + (((0 + kt) ^ (r & 7)) << 4));
        }

#pragma unroll
        for (int kk = 0; kk < BK / 16; ++kk) {
            if (kk < BK / 16 - 1) {            // prefetch A for kk+1
#pragma unroll
                for (int mt = 0; mt < 4; ++mt) {
                    int r = a_row[mt];
                    ldsm_x4(af[(kk + 1) & 1][mt],
                            sa + r * 128 + ((((kk + 1) * 2 + kt) ^ (r & 7)) << 4));
                }
            }
            // B fragments for kk (paired x4: r0=(ntE,k0),r1=(ntO,k0),r2=(ntE,k1),r3=(ntO,k1))
#pragma unroll
            for (int p = 0; p < 2; ++p) {
                int r = b_row[p];
                ldsm_x4(bp[p], sb + r * 128 + (((kk * 2 + kt) ^ (r & 7)) << 4));
            }
#pragma unroll
            for (int mt = 0; mt < 4; ++mt)
#pragma unroll
                for (int nt = 0; nt < 4; ++nt)
                    mma_f16(acc[mt][nt], af[kk & 1][mt],
                            bp[nt >> 1][nt & 1], bp[nt >> 1][(nt & 1) + 2]);
        }
    }

    // Epilogue
#pragma unroll
    for (int mt = 0; mt < 4; ++mt) {
        int r0 = m0 + wm * 64 + mt * 16 + g;
#pragma unroll
        for (int nt = 0; nt < 4; ++nt) {
            int col = n0 + wn * 32 + nt * 8 + 2 * tg;
            *(float2*)(C + (size_t)r0 * OUT_F + col) =
                make_float2(acc[mt][nt][0], acc[mt][nt][1]);
            *(float2*)(C + (size_t)(r0 + 8) * OUT_F + col) =
                make_float2(acc[mt][nt][2], acc[mt][nt][3]);
        }
    }
}

// ---------------------------------------------------------------------------
extern "C" void kernel_launch(void* const* d_in, const int* in_sizes, int n_in,
                              void* d_out, int out_size) {
    const float* x    = (const float*)d_in[0];
    const float* grid = (const float*)d_in[1];
    const float* bw   = (const float*)d_in[2];
    const float* sw   = (const float*)d_in[3];
    const float* sc   = (const float*)d_in[4];
    float* out = (float*)d_out;

    prep_all<<<W_BLOCKS + ACT_BLOCKS, 256>>>(x, grid, bw, sw, sc);

    cudaFuncSetAttribute(kan_gemm, cudaFuncAttributeMaxDynamicSharedMemorySize, GEMM_SMEM);
    dim3 grd(OUT_F / BN, BATCH / BM);   // 4 x 64 = 256 CTAs
    kan_gemm<<<grd, 512, GEMM_SMEM>>>(out);
}